// round 5
// baseline (speedup 1.0000x reference)
#include <cuda_runtime.h>
#include <cuda_bf16.h>
#include <cstdint>
#include <math.h>

// ---------------- problem constants ----------------
#define HID  2048
#define DFF  8192
#define NEXP 8
#define NTOK 8192            // B*S = 4*2048
#define SLOTS (2*NTOK)       // top-2 => 16384 token-expert slots

// ---------------- device scratch (no allocs allowed) ----------------
__device__ int   g_count[NEXP];
__device__ int   g_offset[NEXP];
__device__ int   g_tok_idx[2*NTOK];     // per-token top2 expert ids
__device__ float g_tok_w[2*NTOK];       // per-token top2 weights
__device__ int   g_list_token[SLOTS];   // compacted per-expert token lists
__device__ float g_list_w[SLOTS];
__device__ float g_hmid[(size_t)SLOTS * DFF];   // 512 MB fp32 intermediate

// ---------------- helpers ----------------
__device__ __forceinline__ uint32_t f2tf(float f) {
    uint32_t r;
    asm("cvt.rna.tf32.f32 %0, %1;" : "=r"(r) : "f"(f));
    return r;
}

__device__ __forceinline__ void mma_tf32(float c[4],
                                         uint32_t a0, uint32_t a1, uint32_t a2, uint32_t a3,
                                         uint32_t b0, uint32_t b1) {
    asm volatile(
        "mma.sync.aligned.m16n8k8.row.col.f32.tf32.tf32.f32 "
        "{%0,%1,%2,%3}, {%4,%5,%6,%7}, {%8,%9}, {%0,%1,%2,%3};\n"
        : "+f"(c[0]), "+f"(c[1]), "+f"(c[2]), "+f"(c[3])
        : "r"(a0), "r"(a1), "r"(a2), "r"(a3), "r"(b0), "r"(b1));
}

__device__ __forceinline__ float gelu_f(float v) {
    // jax.nn.gelu approximate=True (tanh form)
    float v3 = v * v * v;
    return 0.5f * v * (1.0f + tanhf(0.7978845608028654f * (v + 0.044715f * v3)));
}

// ---------------- kernel 0: init ----------------
__global__ void init_kernel(float* __restrict__ out) {
    size_t n4 = (size_t)NTOK * HID / 4;
    size_t stride = (size_t)gridDim.x * blockDim.x;
    float4 z = make_float4(0.f, 0.f, 0.f, 0.f);
    for (size_t i = (size_t)blockIdx.x * blockDim.x + threadIdx.x; i < n4; i += stride)
        reinterpret_cast<float4*>(out)[i] = z;
    if (blockIdx.x == 0 && threadIdx.x < NEXP) g_count[threadIdx.x] = 0;
}

// ---------------- kernel 1: router ----------------
// one warp per token: logits = x[t] @ w_gate, softmax fp32, top-2
__global__ void router_kernel(const float* __restrict__ x,
                              const float* __restrict__ wg,
                              float* __restrict__ logits_out) {
    int warp = threadIdx.x >> 5;
    int lane = threadIdx.x & 31;
    int t = blockIdx.x * 8 + warp;
    if (t >= NTOK) return;

    const float* xr = x + (size_t)t * HID;
    float acc[NEXP];
#pragma unroll
    for (int e = 0; e < NEXP; e++) acc[e] = 0.f;

    for (int h = lane; h < HID; h += 32) {
        float xv = xr[h];
        float4 g0 = *reinterpret_cast<const float4*>(wg + (size_t)h * NEXP);
        float4 g1 = *reinterpret_cast<const float4*>(wg + (size_t)h * NEXP + 4);
        acc[0] += xv * g0.x; acc[1] += xv * g0.y; acc[2] += xv * g0.z; acc[3] += xv * g0.w;
        acc[4] += xv * g1.x; acc[5] += xv * g1.y; acc[6] += xv * g1.z; acc[7] += xv * g1.w;
    }
#pragma unroll
    for (int e = 0; e < NEXP; e++)
#pragma unroll
        for (int s = 16; s > 0; s >>= 1)
            acc[e] += __shfl_xor_sync(0xffffffffu, acc[e], s);

    if (lane == 0) {
        float mx = acc[0];
#pragma unroll
        for (int e = 1; e < NEXP; e++) mx = fmaxf(mx, acc[e]);
        float p[NEXP];
        float s = 0.f;
#pragma unroll
        for (int e = 0; e < NEXP; e++) { p[e] = expf(acc[e] - mx); s += p[e]; }
        float inv = 1.f / s;
#pragma unroll
        for (int e = 0; e < NEXP; e++) p[e] *= inv;

        int i0 = 0;
#pragma unroll
        for (int e = 1; e < NEXP; e++) if (p[e] > p[i0]) i0 = e;
        int i1 = (i0 == 0) ? 1 : 0;
#pragma unroll
        for (int e = 0; e < NEXP; e++) if (e != i0 && p[e] > p[i1]) i1 = e;

        g_tok_idx[2*t+0] = i0; g_tok_idx[2*t+1] = i1;
        g_tok_w[2*t+0] = p[i0]; g_tok_w[2*t+1] = p[i1];
        atomicAdd(&g_count[i0], 1);
        atomicAdd(&g_count[i1], 1);
#pragma unroll
        for (int e = 0; e < NEXP; e++) logits_out[(size_t)t * NEXP + e] = acc[e];
    }
}

// ---------------- kernel 2: deterministic compaction ----------------
// one block per expert; token-order-preserving ballot scan
__global__ void compact_kernel() {
    int e = blockIdx.x;
    int tid = threadIdx.x;
    int lane = tid & 31;
    int w = tid >> 5;

    __shared__ int warp_sum[8];
    __shared__ int base_s;

    if (tid == 0) {
        int off = 0;
        for (int i = 0; i < e; i++) off += g_count[i];
        g_offset[e] = off;
        base_s = off;
    }
    __syncthreads();

    for (int t0 = 0; t0 < NTOK; t0 += 256) {
        int t = t0 + tid;
        int i0 = g_tok_idx[2*t];
        int i1 = g_tok_idx[2*t+1];
        bool f0 = (i0 == e);
        bool f  = f0 || (i1 == e);
        unsigned m = __ballot_sync(0xffffffffu, f);
        int pos = __popc(m & ((1u << lane) - 1u));
        if (lane == 31) warp_sum[w] = __popc(m);
        __syncthreads();
        int wbase = 0;
        for (int i = 0; i < w; i++) wbase += warp_sum[i];
        if (f) {
            int p = base_s + wbase + pos;
            g_list_token[p] = t;
            g_list_w[p] = f0 ? g_tok_w[2*t] : g_tok_w[2*t+1];
        }
        __syncthreads();
        if (tid == 0) {
            int tot = 0;
            for (int i = 0; i < 8; i++) tot += warp_sum[i];
            base_s += tot;
        }
        __syncthreads();
    }
}

// ---------------- GEMM tiling config ----------------
// block tile 128x128x16, 8 warps (2 M x 4 N), warp tile 64x32, mma m16n8k8 tf32
#define BM 128
#define BN 128
#define BK 16
#define AS_STR 20    // As[m][k] row stride (16 + 4 pad) -> conflict-free frag loads
#define BS_STR 136   // Bs[k][n] row stride (128 + 8 pad)

// ---------------- kernel 3: GEMM1  hmid = gelu(gather(X) @ W1[e]) ----------------
__global__ __launch_bounds__(256, 2)
void gemm1_kernel(const float* __restrict__ x, const float* __restrict__ w1) {
    int e = blockIdx.z;
    int cnt = g_count[e];
    int m0 = blockIdx.x * BM;
    if (m0 >= cnt) return;
    int off = g_offset[e];
    int n0 = blockIdx.y * BN;
    const float* W = w1 + (size_t)e * HID * DFF;

    __shared__ int toks[BM];
    __shared__ uint32_t As[2][BM][AS_STR];
    __shared__ uint32_t Bs[2][BK][BS_STR];

    int tid = threadIdx.x;
    if (tid < BM) {
        int r = m0 + tid;
        toks[tid] = g_list_token[off + min(r, cnt - 1)];
    }
    __syncthreads();

    // loader mapping
    int ar = tid >> 2;              // A row (first 64), +64 for second
    int ac = (tid & 3) * 4;         // A col within 16-k tile
    int brow = tid >> 5;            // B k-row (first 8), +8 for second
    int bcol = (tid & 31) * 4;      // B n-col
    size_t tA = (size_t)toks[ar];
    size_t tB = (size_t)toks[ar + 64];

    // prologue: stage 0
    float4 a0v = *reinterpret_cast<const float4*>(x + tA * HID + 0 + ac);
    float4 a1v = *reinterpret_cast<const float4*>(x + tB * HID + 0 + ac);
    float4 b0v = *reinterpret_cast<const float4*>(W + (size_t)(0 + brow) * DFF + n0 + bcol);
    float4 b1v = *reinterpret_cast<const float4*>(W + (size_t)(8 + brow) * DFF + n0 + bcol);
    As[0][ar][ac+0] = f2tf(a0v.x); As[0][ar][ac+1] = f2tf(a0v.y);
    As[0][ar][ac+2] = f2tf(a0v.z); As[0][ar][ac+3] = f2tf(a0v.w);
    As[0][ar+64][ac+0] = f2tf(a1v.x); As[0][ar+64][ac+1] = f2tf(a1v.y);
    As[0][ar+64][ac+2] = f2tf(a1v.z); As[0][ar+64][ac+3] = f2tf(a1v.w);
    Bs[0][brow][bcol+0] = f2tf(b0v.x); Bs[0][brow][bcol+1] = f2tf(b0v.y);
    Bs[0][brow][bcol+2] = f2tf(b0v.z); Bs[0][brow][bcol+3] = f2tf(b0v.w);
    Bs[0][brow+8][bcol+0] = f2tf(b1v.x); Bs[0][brow+8][bcol+1] = f2tf(b1v.y);
    Bs[0][brow+8][bcol+2] = f2tf(b1v.z); Bs[0][brow+8][bcol+3] = f2tf(b1v.w);
    __syncthreads();

    int lane = tid & 31;
    int gid = lane >> 2, t4 = lane & 3;
    int w = tid >> 5;
    int wm = (w & 1) * 64;
    int wn = (w >> 1) * 32;

    float c[4][4][4];
#pragma unroll
    for (int mt = 0; mt < 4; mt++)
#pragma unroll
        for (int nt = 0; nt < 4; nt++)
#pragma unroll
            for (int i = 0; i < 4; i++) c[mt][nt][i] = 0.f;

    const int KT = HID / BK;   // 128
    for (int kt = 0; kt < KT; kt++) {
        int buf = kt & 1;
        if (kt + 1 < KT) {
            int k0 = (kt + 1) * BK;
            a0v = *reinterpret_cast<const float4*>(x + tA * HID + k0 + ac);
            a1v = *reinterpret_cast<const float4*>(x + tB * HID + k0 + ac);
            b0v = *reinterpret_cast<const float4*>(W + (size_t)(k0 + brow) * DFF + n0 + bcol);
            b1v = *reinterpret_cast<const float4*>(W + (size_t)(k0 + 8 + brow) * DFF + n0 + bcol);
        }
#pragma unroll
        for (int ks = 0; ks < BK; ks += 8) {
            uint32_t a[4][4], b[4][2];
#pragma unroll
            for (int mt = 0; mt < 4; mt++) {
                int m = wm + mt * 16;
                a[mt][0] = As[buf][m + gid    ][ks + t4];
                a[mt][1] = As[buf][m + gid + 8][ks + t4];
                a[mt][2] = As[buf][m + gid    ][ks + t4 + 4];
                a[mt][3] = As[buf][m + gid + 8][ks + t4 + 4];
            }
#pragma unroll
            for (int nt = 0; nt < 4; nt++) {
                int n = wn + nt * 8;
                b[nt][0] = Bs[buf][ks + t4    ][n + gid];
                b[nt][1] = Bs[buf][ks + t4 + 4][n + gid];
            }
#pragma unroll
            for (int mt = 0; mt < 4; mt++)
#pragma unroll
                for (int nt = 0; nt < 4; nt++)
                    mma_tf32(c[mt][nt], a[mt][0], a[mt][1], a[mt][2], a[mt][3],
                             b[nt][0], b[nt][1]);
        }
        if (kt + 1 < KT) {
            int nb = buf ^ 1;
            As[nb][ar][ac+0] = f2tf(a0v.x); As[nb][ar][ac+1] = f2tf(a0v.y);
            As[nb][ar][ac+2] = f2tf(a0v.z); As[nb][ar][ac+3] = f2tf(a0v.w);
            As[nb][ar+64][ac+0] = f2tf(a1v.x); As[nb][ar+64][ac+1] = f2tf(a1v.y);
            As[nb][ar+64][ac+2] = f2tf(a1v.z); As[nb][ar+64][ac+3] = f2tf(a1v.w);
            Bs[nb][brow][bcol+0] = f2tf(b0v.x); Bs[nb][brow][bcol+1] = f2tf(b0v.y);
            Bs[nb][brow][bcol+2] = f2tf(b0v.z); Bs[nb][brow][bcol+3] = f2tf(b0v.w);
            Bs[nb][brow+8][bcol+0] = f2tf(b1v.x); Bs[nb][brow+8][bcol+1] = f2tf(b1v.y);
            Bs[nb][brow+8][bcol+2] = f2tf(b1v.z); Bs[nb][brow+8][bcol+3] = f2tf(b1v.w);
        }
        __syncthreads();
    }

    // epilogue: gelu + store to hmid scratch
#pragma unroll
    for (int mt = 0; mt < 4; mt++)
#pragma unroll
        for (int nt = 0; nt < 4; nt++) {
            int col = n0 + wn + nt * 8 + t4 * 2;
#pragma unroll
            for (int h = 0; h < 2; h++) {
                int row = wm + mt * 16 + gid + h * 8;
                int gr = m0 + row;
                if (gr < cnt) {
                    float2 v;
                    v.x = gelu_f(c[mt][nt][h * 2 + 0]);
                    v.y = gelu_f(c[mt][nt][h * 2 + 1]);
                    *reinterpret_cast<float2*>(&g_hmid[(size_t)(off + gr) * DFF + col]) = v;
                }
            }
        }
}

// ---------------- kernel 4: GEMM2  out += w * (hmid @ W2[e]) ----------------
__global__ __launch_bounds__(256, 2)
void gemm2_kernel(const float* __restrict__ w2, float* __restrict__ out) {
    int e = blockIdx.z;
    int cnt = g_count[e];
    int m0 = blockIdx.x * BM;
    if (m0 >= cnt) return;
    int off = g_offset[e];
    int n0 = blockIdx.y * BN;
    const float* W = w2 + (size_t)e * DFF * HID;

    __shared__ int   toks[BM];
    __shared__ float wts[BM];
    __shared__ uint32_t As[2][BM][AS_STR];
    __shared__ uint32_t Bs[2][BK][BS_STR];

    int tid = threadIdx.x;
    if (tid < BM) {
        int r = m0 + tid;
        int rc = min(r, cnt - 1);
        toks[tid] = g_list_token[off + rc];
        wts[tid]  = g_list_w[off + rc];
    }

    int ar = tid >> 2;
    int ac = (tid & 3) * 4;
    int brow = tid >> 5;
    int bcol = (tid & 31) * 4;
    const float* arowA = g_hmid + (size_t)(off + min(m0 + ar,      cnt - 1)) * DFF;
    const float* arowB = g_hmid + (size_t)(off + min(m0 + ar + 64, cnt - 1)) * DFF;

    float4 a0v = *reinterpret_cast<const float4*>(arowA + 0 + ac);
    float4 a1v = *reinterpret_cast<const float4*>(arowB + 0 + ac);
    float4 b0v = *reinterpret_cast<const float4*>(W + (size_t)(0 + brow) * HID + n0 + bcol);
    float4 b1v = *reinterpret_cast<const float4*>(W + (size_t)(8 + brow) * HID + n0 + bcol);
    As[0][ar][ac+0] = f2tf(a0v.x); As[0][ar][ac+1] = f2tf(a0v.y);
    As[0][ar][ac+2] = f2tf(a0v.z); As[0][ar][ac+3] = f2tf(a0v.w);
    As[0][ar+64][ac+0] = f2tf(a1v.x); As[0][ar+64][ac+1] = f2tf(a1v.y);
    As[0][ar+64][ac+2] = f2tf(a1v.z); As[0][ar+64][ac+3] = f2tf(a1v.w);
    Bs[0][brow][bcol+0] = f2tf(b0v.x); Bs[0][brow][bcol+1] = f2tf(b0v.y);
    Bs[0][brow][bcol+2] = f2tf(b0v.z); Bs[0][brow][bcol+3] = f2tf(b0v.w);
    Bs[0][brow+8][bcol+0] = f2tf(b1v.x); Bs[0][brow+8][bcol+1] = f2tf(b1v.y);
    Bs[0][brow+8][bcol+2] = f2tf(b1v.z); Bs[0][brow+8][bcol+3] = f2tf(b1v.w);
    __syncthreads();

    int lane = tid & 31;
    int gid = lane >> 2, t4 = lane & 3;
    int w = tid >> 5;
    int wm = (w & 1) * 64;
    int wn = (w >> 1) * 32;

    float c[4][4][4];
#pragma unroll
    for (int mt = 0; mt < 4; mt++)
#pragma unroll
        for (int nt = 0; nt < 4; nt++)
#pragma unroll
            for (int i = 0; i < 4; i++) c[mt][nt][i] = 0.f;

    const int KT = DFF / BK;   // 512
    for (int kt = 0; kt < KT; kt++) {
        int buf = kt & 1;
        if (kt + 1 < KT) {
            int k0 = (kt + 1) * BK;
            a0v = *reinterpret_cast<const float4*>(arowA + k0 + ac);
            a1v = *reinterpret_cast<const float4*>(arowB + k0 + ac);
            b0v = *reinterpret_cast<const float4*>(W + (size_t)(k0 + brow) * HID + n0 + bcol);
            b1v = *reinterpret_cast<const float4*>(W + (size_t)(k0 + 8 + brow) * HID + n0 + bcol);
        }
#pragma unroll
        for (int ks = 0; ks < BK; ks += 8) {
            uint32_t a[4][4], b[4][2];
#pragma unroll
            for (int mt = 0; mt < 4; mt++) {
                int m = wm + mt * 16;
                a[mt][0] = As[buf][m + gid    ][ks + t4];
                a[mt][1] = As[buf][m + gid + 8][ks + t4];
                a[mt][2] = As[buf][m + gid    ][ks + t4 + 4];
                a[mt][3] = As[buf][m + gid + 8][ks + t4 + 4];
            }
#pragma unroll
            for (int nt = 0; nt < 4; nt++) {
                int n = wn + nt * 8;
                b[nt][0] = Bs[buf][ks + t4    ][n + gid];
                b[nt][1] = Bs[buf][ks + t4 + 4][n + gid];
            }
#pragma unroll
            for (int mt = 0; mt < 4; mt++)
#pragma unroll
                for (int nt = 0; nt < 4; nt++)
                    mma_tf32(c[mt][nt], a[mt][0], a[mt][1], a[mt][2], a[mt][3],
                             b[nt][0], b[nt][1]);
        }
        if (kt + 1 < KT) {
            int nb = buf ^ 1;
            As[nb][ar][ac+0] = f2tf(a0v.x); As[nb][ar][ac+1] = f2tf(a0v.y);
            As[nb][ar][ac+2] = f2tf(a0v.z); As[nb][ar][ac+3] = f2tf(a0v.w);
            As[nb][ar+64][ac+0] = f2tf(a1v.x); As[nb][ar+64][ac+1] = f2tf(a1v.y);
            As[nb][ar+64][ac+2] = f2tf(a1v.z); As[nb][ar+64][ac+3] = f2tf(a1v.w);
            Bs[nb][brow][bcol+0] = f2tf(b0v.x); Bs[nb][brow][bcol+1] = f2tf(b0v.y);
            Bs[nb][brow][bcol+2] = f2tf(b0v.z); Bs[nb][brow][bcol+3] = f2tf(b0v.w);
            Bs[nb][brow+8][bcol+0] = f2tf(b1v.x); Bs[nb][brow+8][bcol+1] = f2tf(b1v.y);
            Bs[nb][brow+8][bcol+2] = f2tf(b1v.z); Bs[nb][brow+8][bcol+3] = f2tf(b1v.w);
        }
        __syncthreads();
    }

    // epilogue: weighted atomic scatter into out
#pragma unroll
    for (int mt = 0; mt < 4; mt++)
#pragma unroll
        for (int nt = 0; nt < 4; nt++) {
            int col = n0 + wn + nt * 8 + t4 * 2;
#pragma unroll
            for (int h = 0; h < 2; h++) {
                int row = wm + mt * 16 + gid + h * 8;
                int gr = m0 + row;
                if (gr < cnt) {
                    int tok = toks[row];
                    float wt = wts[row];
                    float* o = out + (size_t)tok * HID + col;
                    atomicAdd(o + 0, wt * c[mt][nt][h * 2 + 0]);
                    atomicAdd(o + 1, wt * c[mt][nt][h * 2 + 1]);
                }
            }
        }
}

// ---------------- launch ----------------
extern "C" void kernel_launch(void* const* d_in, const int* in_sizes, int n_in,
                              void* d_out, int out_size) {
    const float* x  = (const float*)d_in[0];   // [B,S,H] fp32
    const float* wg = (const float*)d_in[1];   // [H,E]
    const float* w1 = (const float*)d_in[2];   // [E,H,DFF]
    const float* w2 = (const float*)d_in[3];   // [E,DFF,H]
    float* out    = (float*)d_out;                      // [T,H] first
    float* logits = out + (size_t)NTOK * HID;           // [T,E] second

    init_kernel<<<2048, 256>>>(out);
    router_kernel<<<NTOK / 8, 256>>>(x, wg, logits);
    compact_kernel<<<NEXP, 256>>>();
    gemm1_kernel<<<dim3(NTOK / BM, DFF / BN, NEXP), 256>>>(x, w1);
    gemm2_kernel<<<dim3(NTOK / BM, HID / BN, NEXP), 256>>>(w2, out);
}

// round 7
// speedup vs baseline: 2.0215x; 2.0215x over previous
#include <cuda_runtime.h>
#include <cuda_fp16.h>
#include <cstdint>
#include <math.h>

// ---------------- problem constants ----------------
#define HID  2048
#define DFF  8192
#define NEXP 8
#define NTOK 8192
#define SLOTS (2*NTOK)

// ---------------- device scratch (no allocs allowed) ----------------
__device__ int    g_count[NEXP];
__device__ int    g_offset[NEXP];
__device__ int    g_tok_idx[2*NTOK];
__device__ float  g_tok_w[2*NTOK];
__device__ int    g_tok_slot[2*NTOK];
__device__ int    g_list_token[SLOTS];
__device__ __half g_hmid[(size_t)SLOTS * DFF];  // 256 MB fp16 intermediate
__device__ float  g_ysl [(size_t)SLOTS * HID];  // 128 MB per-slot expert output

// ---------------- helpers ----------------
__device__ __forceinline__ uint32_t smem_u32(const void* p) {
    uint32_t a;
    asm("{ .reg .u64 t; cvta.to.shared.u64 t, %1; cvt.u32.u64 %0, t; }" : "=r"(a) : "l"(p));
    return a;
}
__device__ __forceinline__ uint32_t f2h2(float lo, float hi) {
    __half2 h = __floats2half2_rn(lo, hi);
    return *reinterpret_cast<uint32_t*>(&h);
}
__device__ __forceinline__ float gelu_f(float v) {
    float v3 = v * v * v;
    return 0.5f * v * (1.0f + tanhf(0.7978845608028654f * (v + 0.044715f * v3)));
}

#define LDSM_X4(r, addr) \
    asm volatile("ldmatrix.sync.aligned.m8n8.x4.shared.b16 {%0,%1,%2,%3}, [%4];" \
        : "=r"((r)[0]), "=r"((r)[1]), "=r"((r)[2]), "=r"((r)[3]) : "r"(addr))
#define LDSM_X4T(r0, r1, r2, r3, addr) \
    asm volatile("ldmatrix.sync.aligned.m8n8.x4.trans.shared.b16 {%0,%1,%2,%3}, [%4];" \
        : "=r"(r0), "=r"(r1), "=r"(r2), "=r"(r3) : "r"(addr))
#define MMA_F16(c, a, b) \
    asm volatile("mma.sync.aligned.m16n8k16.row.col.f32.f16.f16.f32 " \
        "{%0,%1,%2,%3},{%4,%5,%6,%7},{%8,%9},{%0,%1,%2,%3};" \
        : "+f"((c)[0]), "+f"((c)[1]), "+f"((c)[2]), "+f"((c)[3]) \
        : "r"((a)[0]), "r"((a)[1]), "r"((a)[2]), "r"((a)[3]), "r"((b)[0]), "r"((b)[1]))

// ---------------- kernel: zero counts ----------------
__global__ void zcount_kernel() {
    if (threadIdx.x < NEXP) g_count[threadIdx.x] = 0;
}

// ---------------- kernel: router ----------------
__global__ void router_kernel(const float* __restrict__ x,
                              const float* __restrict__ wg,
                              float* __restrict__ logits_out) {
    int warp = threadIdx.x >> 5;
    int lane = threadIdx.x & 31;
    int t = blockIdx.x * 8 + warp;
    if (t >= NTOK) return;

    const float* xr = x + (size_t)t * HID;
    float acc[NEXP];
#pragma unroll
    for (int e = 0; e < NEXP; e++) acc[e] = 0.f;
    for (int h = lane; h < HID; h += 32) {
        float xv = xr[h];
        float4 g0 = *reinterpret_cast<const float4*>(wg + (size_t)h * NEXP);
        float4 g1 = *reinterpret_cast<const float4*>(wg + (size_t)h * NEXP + 4);
        acc[0] += xv * g0.x; acc[1] += xv * g0.y; acc[2] += xv * g0.z; acc[3] += xv * g0.w;
        acc[4] += xv * g1.x; acc[5] += xv * g1.y; acc[6] += xv * g1.z; acc[7] += xv * g1.w;
    }
#pragma unroll
    for (int e = 0; e < NEXP; e++)
#pragma unroll
        for (int s = 16; s > 0; s >>= 1)
            acc[e] += __shfl_xor_sync(0xffffffffu, acc[e], s);

    if (lane == 0) {
        float mx = acc[0];
#pragma unroll
        for (int e = 1; e < NEXP; e++) mx = fmaxf(mx, acc[e]);
        float p[NEXP], s = 0.f;
#pragma unroll
        for (int e = 0; e < NEXP; e++) { p[e] = expf(acc[e] - mx); s += p[e]; }
        float inv = 1.f / s;
#pragma unroll
        for (int e = 0; e < NEXP; e++) p[e] *= inv;

        int i0 = 0;
#pragma unroll
        for (int e = 1; e < NEXP; e++) if (p[e] > p[i0]) i0 = e;
        int i1 = (i0 == 0) ? 1 : 0;
#pragma unroll
        for (int e = 0; e < NEXP; e++) if (e != i0 && p[e] > p[i1]) i1 = e;

        g_tok_idx[2*t+0] = i0; g_tok_idx[2*t+1] = i1;
        g_tok_w[2*t+0] = p[i0]; g_tok_w[2*t+1] = p[i1];
        atomicAdd(&g_count[i0], 1);
        atomicAdd(&g_count[i1], 1);
#pragma unroll
        for (int e = 0; e < NEXP; e++) logits_out[(size_t)t * NEXP + e] = acc[e];
    }
}

// ---------------- kernel: deterministic compaction (+slot map) ----------------
__global__ void compact_kernel() {
    int e = blockIdx.x;
    int tid = threadIdx.x;
    int lane = tid & 31;
    int w = tid >> 5;

    __shared__ int warp_sum[8];
    __shared__ int base_s;

    if (tid == 0) {
        int off = 0;
        for (int i = 0; i < e; i++) off += g_count[i];
        g_offset[e] = off;
        base_s = off;
    }
    __syncthreads();

    for (int t0 = 0; t0 < NTOK; t0 += 256) {
        int t = t0 + tid;
        int i0 = g_tok_idx[2*t];
        int i1 = g_tok_idx[2*t+1];
        bool f0 = (i0 == e);
        bool f  = f0 || (i1 == e);
        unsigned m = __ballot_sync(0xffffffffu, f);
        int pos = __popc(m & ((1u << lane) - 1u));
        if (lane == 31) warp_sum[w] = __popc(m);
        __syncthreads();
        int wbase = 0;
        for (int i = 0; i < w; i++) wbase += warp_sum[i];
        if (f) {
            int p = base_s + wbase + pos;
            g_list_token[p] = t;
            g_tok_slot[2*t + (f0 ? 0 : 1)] = p;
        }
        __syncthreads();
        if (tid == 0) {
            int tot = 0;
            for (int i = 0; i < 8; i++) tot += warp_sum[i];
            base_s += tot;
        }
        __syncthreads();
    }
}

// ---------------- fp16 tensor-core GEMM: block 128x128, BK=32 ----------------
// A smem: [128 m][32 k] fp16, 64B rows, chunk swizzle kc ^= (m>>1)&3
// B smem: [32 k][128 n] fp16, 256B rows, chunk swizzle nc ^= k&7
// 8 warps (2M x 4N), warp tile 64x32, mma m16n8k16 via ldmatrix(+trans)
#define BM 128
#define BN 128
#define BKH 32
#define ABUF 8192
#define BBUF 8192

template<int KTOT, int BSTR, bool G1>
__global__ __launch_bounds__(256, 2)
void moe_gemm(const float* __restrict__ X, const float* __restrict__ W) {
    __shared__ __align__(128) uint8_t As[2 * ABUF];
    __shared__ __align__(128) uint8_t Bs[2 * BBUF];
    __shared__ int toks[BM];

    const int e   = blockIdx.z;
    const int cnt = g_count[e];
    const int m0  = blockIdx.x * BM;
    if (m0 >= cnt) return;
    const int off = g_offset[e];
    const int n0  = blockIdx.y * BN;
    const float* Wexp = W + (size_t)e * KTOT * BSTR;

    const int tid = threadIdx.x;
    if (G1) {
        if (tid < BM) toks[tid] = g_list_token[off + min(m0 + tid, cnt - 1)];
        __syncthreads();
    }

    // ---- loader mapping ----
    const int lm = tid >> 1;            // A row 0..127
    const int kh = (tid & 1) * 16;      // k half within stage
    const float* arow = nullptr;
    const uint4* arow2 = nullptr;
    if (G1) arow  = X + (size_t)toks[lm] * KTOT + kh;
    else    arow2 = reinterpret_cast<const uint4*>(
                        g_hmid + (size_t)(off + min(m0 + lm, cnt - 1)) * KTOT + kh);
    const int rswm = (lm >> 1) & 3;
    const int sA0 = lm * 64 + ((((kh >> 3) + 0) ^ rswm) << 4);
    const int sA1 = lm * 64 + ((((kh >> 3) + 1) ^ rswm) << 4);

    const int bk  = tid >> 3;           // B k row 0..31
    const int bnb = (tid & 7) * 16;     // B n base (elements)
    const int sB0 = bk * 256 + ((((tid & 7) * 2 + 0) ^ (bk & 7)) << 4);
    const int sB1 = bk * 256 + ((((tid & 7) * 2 + 1) ^ (bk & 7)) << 4);

    // ---- mma fragment addresses ----
    const int lane = tid & 31;
    const int wid  = tid >> 5;
    const int wm   = (wid & 1) * 64;
    const int wn   = (wid >> 1) * 32;
    const int gid  = lane >> 2;
    const int t4   = lane & 3;

    const uint32_t aBase = smem_u32(As);
    const uint32_t bBase = smem_u32(Bs);
    const int ar16 = lane & 15;
    const int rswL = (ar16 >> 1) & 3;
    const int k2b  = lane >> 4;
    uint32_t addrA[4][2];
#pragma unroll
    for (int mt = 0; mt < 4; mt++)
#pragma unroll
        for (int h = 0; h < 2; h++)
            addrA[mt][h] = aBase + (wm + mt * 16 + ar16) * 64
                         + (((h * 2 + k2b) ^ rswL) << 4);
    const int kb   = lane & 15;
    const int nadd = (lane >> 4) * 8;
    uint32_t addrB[2][2];
#pragma unroll
    for (int np = 0; np < 2; np++)
#pragma unroll
        for (int h = 0; h < 2; h++) {
            int nc = (wn + np * 16 + nadd) >> 3;
            addrB[np][h] = bBase + (h * 16 + kb) * 256 + ((nc ^ (kb & 7)) << 4);
        }

    // ---- prefetch machinery ----
    uint4 pa0, pa1, pb0, pb1;
#define PREFETCH(k0) do {                                                        \
    if (G1) {                                                                    \
        float4 f0 = *reinterpret_cast<const float4*>(arow + (k0));               \
        float4 f1 = *reinterpret_cast<const float4*>(arow + (k0) + 4);           \
        float4 f2 = *reinterpret_cast<const float4*>(arow + (k0) + 8);           \
        float4 f3 = *reinterpret_cast<const float4*>(arow + (k0) + 12);          \
        pa0 = make_uint4(f2h2(f0.x,f0.y), f2h2(f0.z,f0.w),                       \
                         f2h2(f1.x,f1.y), f2h2(f1.z,f1.w));                      \
        pa1 = make_uint4(f2h2(f2.x,f2.y), f2h2(f2.z,f2.w),                       \
                         f2h2(f3.x,f3.y), f2h2(f3.z,f3.w));                      \
    } else {                                                                     \
        pa0 = arow2[(k0) >> 3];                                                  \
        pa1 = arow2[((k0) >> 3) + 1];                                            \
    }                                                                            \
    {                                                                            \
        const float* bp = Wexp + (size_t)((k0) + bk) * BSTR + n0 + bnb;          \
        float4 f0 = *reinterpret_cast<const float4*>(bp);                        \
        float4 f1 = *reinterpret_cast<const float4*>(bp + 4);                    \
        float4 f2 = *reinterpret_cast<const float4*>(bp + 8);                    \
        float4 f3 = *reinterpret_cast<const float4*>(bp + 12);                   \
        pb0 = make_uint4(f2h2(f0.x,f0.y), f2h2(f0.z,f0.w),                       \
                         f2h2(f1.x,f1.y), f2h2(f1.z,f1.w));                      \
        pb1 = make_uint4(f2h2(f2.x,f2.y), f2h2(f2.z,f2.w),                       \
                         f2h2(f3.x,f3.y), f2h2(f3.z,f3.w));                      \
    }                                                                            \
} while (0)
#define STAGE_STORE(nb) do {                                                     \
    *reinterpret_cast<uint4*>(As + (nb) * ABUF + sA0) = pa0;                     \
    *reinterpret_cast<uint4*>(As + (nb) * ABUF + sA1) = pa1;                     \
    *reinterpret_cast<uint4*>(Bs + (nb) * BBUF + sB0) = pb0;                     \
    *reinterpret_cast<uint4*>(Bs + (nb) * BBUF + sB1) = pb1;                     \
} while (0)

    float c[4][4][4];
#pragma unroll
    for (int mt = 0; mt < 4; mt++)
#pragma unroll
        for (int nt = 0; nt < 4; nt++)
#pragma unroll
            for (int i = 0; i < 4; i++) c[mt][nt][i] = 0.f;

    PREFETCH(0);
    STAGE_STORE(0);
    __syncthreads();

    const int KT = KTOT / BKH;
    for (int kt = 0; kt < KT; kt++) {
        const int buf = kt & 1;
        const uint32_t sb = buf * ABUF;   // ABUF == BBUF
        if (kt + 1 < KT) PREFETCH((kt + 1) * BKH);
#pragma unroll
        for (int h = 0; h < 2; h++) {
            uint32_t a[4][4], b[4][2];
#pragma unroll
            for (int mt = 0; mt < 4; mt++) LDSM_X4(a[mt], addrA[mt][h] + sb);
#pragma unroll
            for (int np = 0; np < 2; np++)
                LDSM_X4T(b[2*np][0], b[2*np][1], b[2*np+1][0], b[2*np+1][1],
                         addrB[np][h] + sb);
#pragma unroll
            for (int mt = 0; mt < 4; mt++)
#pragma unroll
                for (int nt = 0; nt < 4; nt++)
                    MMA_F16(c[mt][nt], a[mt], b[nt]);
        }
        if (kt + 1 < KT) STAGE_STORE(buf ^ 1);
        __syncthreads();
    }

    // ---- epilogue ----
#pragma unroll
    for (int mt = 0; mt < 4; mt++)
#pragma unroll
        for (int nt = 0; nt < 4; nt++) {
            int col = n0 + wn + nt * 8 + t4 * 2;
#pragma unroll
            for (int hh = 0; hh < 2; hh++) {
                int row = wm + mt * 16 + gid + hh * 8;
                int gr  = m0 + row;
                if (gr < cnt) {
                    float v0 = c[mt][nt][hh * 2 + 0];
                    float v1 = c[mt][nt][hh * 2 + 1];
                    if (G1) {
                        __half2 hv = __floats2half2_rn(gelu_f(v0), gelu_f(v1));
                        *reinterpret_cast<__half2*>(
                            &g_hmid[(size_t)(off + gr) * DFF + col]) = hv;
                    } else {
                        float2 fv; fv.x = v0; fv.y = v1;
                        *reinterpret_cast<float2*>(
                            &g_ysl[(size_t)(off + gr) * HID + col]) = fv;
                    }
                }
            }
        }
#undef PREFETCH
#undef STAGE_STORE
}

// ---------------- kernel: combine (no atomics, overwrites out) ----------------
__global__ void combine_kernel(float* __restrict__ out) {
    int t  = blockIdx.x;
    int s0 = g_tok_slot[2 * t], s1 = g_tok_slot[2 * t + 1];
    float w0 = g_tok_w[2 * t],  w1 = g_tok_w[2 * t + 1];
    const float4* ya = reinterpret_cast<const float4*>(g_ysl + (size_t)s0 * HID);
    const float4* yb = reinterpret_cast<const float4*>(g_ysl + (size_t)s1 * HID);
    float4* o = reinterpret_cast<float4*>(out + (size_t)t * HID);
    for (int i = threadIdx.x; i < HID / 4; i += blockDim.x) {
        float4 a = ya[i], b = yb[i], r;
        r.x = w0 * a.x + w1 * b.x; r.y = w0 * a.y + w1 * b.y;
        r.z = w0 * a.z + w1 * b.z; r.w = w0 * a.w + w1 * b.w;
        o[i] = r;
    }
}

// ---------------- launch ----------------
extern "C" void kernel_launch(void* const* d_in, const int* in_sizes, int n_in,
                              void* d_out, int out_size) {
    const float* x  = (const float*)d_in[0];   // [B,S,H]
    const float* wg = (const float*)d_in[1];   // [H,E]
    const float* w1 = (const float*)d_in[2];   // [E,H,DFF]
    const float* w2 = (const float*)d_in[3];   // [E,DFF,H]
    float* out    = (float*)d_out;                    // [T,H]
    float* logits = out + (size_t)NTOK * HID;         // [T,E]

    zcount_kernel<<<1, 32>>>();
    router_kernel<<<NTOK / 8, 256>>>(x, wg, logits);
    compact_kernel<<<NEXP, 256>>>();
    moe_gemm<HID, DFF, true>
        <<<dim3(SLOTS / BM, DFF / BN, NEXP), 256>>>(x, w1);
    moe_gemm<DFF, HID, false>
        <<<dim3(SLOTS / BM, HID / BN, NEXP), 256>>>(nullptr, w2);
    combine_kernel<<<NTOK, 256>>>(out);
}

// round 9
// speedup vs baseline: 3.5111x; 1.7369x over previous
#include <cuda_runtime.h>
#include <cuda_fp16.h>
#include <cstdint>
#include <math.h>

// ---------------- problem constants ----------------
#define HID  2048
#define DFF  8192
#define NEXP 8
#define NTOK 8192
#define SLOTS (2*NTOK)

// ---------------- device scratch (no allocs allowed) ----------------
__device__ int    g_count[NEXP];
__device__ int    g_offset[NEXP];
__device__ int    g_tok_idx[2*NTOK];
__device__ float  g_tok_w[2*NTOK];
__device__ int    g_tok_slot[2*NTOK];
__device__ int    g_list_token[SLOTS];
__device__ __half g_xh  [(size_t)NTOK * HID];       // 32 MB  fp16 activations
__device__ __half g_w1h [(size_t)NEXP * HID * DFF]; // 256 MB fp16 w1
__device__ __half g_w2h [(size_t)NEXP * DFF * HID]; // 256 MB fp16 w2
__device__ __half g_hmid[(size_t)SLOTS * DFF];      // 256 MB fp16 intermediate
__device__ float  g_ysl [(size_t)SLOTS * HID];      // 128 MB per-slot output

// ---------------- helpers ----------------
__device__ __forceinline__ uint32_t smem_u32(const void* p) {
    uint32_t a;
    asm("{ .reg .u64 t; cvta.to.shared.u64 t, %1; cvt.u32.u64 %0, t; }" : "=r"(a) : "l"(p));
    return a;
}
__device__ __forceinline__ uint32_t f2h2(float lo, float hi) {
    __half2 h = __floats2half2_rn(lo, hi);
    return *reinterpret_cast<uint32_t*>(&h);
}
__device__ __forceinline__ float gelu_f(float v) {
    float v3 = v * v * v;
    return 0.5f * v * (1.0f + tanhf(0.7978845608028654f * (v + 0.044715f * v3)));
}

#define LDSM_X4(r, addr) \
    asm volatile("ldmatrix.sync.aligned.m8n8.x4.shared.b16 {%0,%1,%2,%3}, [%4];" \
        : "=r"((r)[0]), "=r"((r)[1]), "=r"((r)[2]), "=r"((r)[3]) : "r"(addr))
#define LDSM_X4T(r0, r1, r2, r3, addr) \
    asm volatile("ldmatrix.sync.aligned.m8n8.x4.trans.shared.b16 {%0,%1,%2,%3}, [%4];" \
        : "=r"(r0), "=r"(r1), "=r"(r2), "=r"(r3) : "r"(addr))
#define MMA_F16(c, a, b) \
    asm volatile("mma.sync.aligned.m16n8k16.row.col.f32.f16.f16.f32 " \
        "{%0,%1,%2,%3},{%4,%5,%6,%7},{%8,%9},{%0,%1,%2,%3};" \
        : "+f"((c)[0]), "+f"((c)[1]), "+f"((c)[2]), "+f"((c)[3]) \
        : "r"((a)[0]), "r"((a)[1]), "r"((a)[2]), "r"((a)[3]), "r"((b)[0]), "r"((b)[1]))
#define CP16(dst, src) \
    asm volatile("cp.async.cg.shared.global [%0], [%1], 16;" :: "r"(dst), "l"(src))
#define CP_COMMIT() asm volatile("cp.async.commit_group;" ::: "memory")
#define CP_WAIT(n)  asm volatile("cp.async.wait_group %0;" :: "n"(n) : "memory")

// ---------------- kernel: fp32 -> fp16 bulk convert ----------------
__global__ void cvt_fp16_kernel(const float* __restrict__ s, __half* __restrict__ d,
                                size_t n8) {
    size_t i = (size_t)blockIdx.x * blockDim.x + threadIdx.x;
    size_t stride = (size_t)gridDim.x * blockDim.x;
    const float4* s4 = reinterpret_cast<const float4*>(s);
    uint4* d4 = reinterpret_cast<uint4*>(d);
    for (; i < n8; i += stride) {
        float4 f0 = s4[i * 2], f1 = s4[i * 2 + 1];
        uint4 o;
        o.x = f2h2(f0.x, f0.y); o.y = f2h2(f0.z, f0.w);
        o.z = f2h2(f1.x, f1.y); o.w = f2h2(f1.z, f1.w);
        d4[i] = o;
    }
}

// ---------------- kernel: zero counts ----------------
__global__ void zcount_kernel() {
    if (threadIdx.x < NEXP) g_count[threadIdx.x] = 0;
}

// ---------------- kernel: router ----------------
__global__ void router_kernel(const float* __restrict__ x,
                              const float* __restrict__ wg,
                              float* __restrict__ logits_out) {
    int warp = threadIdx.x >> 5;
    int lane = threadIdx.x & 31;
    int t = blockIdx.x * 8 + warp;
    if (t >= NTOK) return;

    const float* xr = x + (size_t)t * HID;
    float acc[NEXP];
#pragma unroll
    for (int e = 0; e < NEXP; e++) acc[e] = 0.f;
    for (int h = lane; h < HID; h += 32) {
        float xv = xr[h];
        float4 g0 = *reinterpret_cast<const float4*>(wg + (size_t)h * NEXP);
        float4 g1 = *reinterpret_cast<const float4*>(wg + (size_t)h * NEXP + 4);
        acc[0] += xv * g0.x; acc[1] += xv * g0.y; acc[2] += xv * g0.z; acc[3] += xv * g0.w;
        acc[4] += xv * g1.x; acc[5] += xv * g1.y; acc[6] += xv * g1.z; acc[7] += xv * g1.w;
    }
#pragma unroll
    for (int e = 0; e < NEXP; e++)
#pragma unroll
        for (int s = 16; s > 0; s >>= 1)
            acc[e] += __shfl_xor_sync(0xffffffffu, acc[e], s);

    if (lane == 0) {
        float mx = acc[0];
#pragma unroll
        for (int e = 1; e < NEXP; e++) mx = fmaxf(mx, acc[e]);
        float p[NEXP], s = 0.f;
#pragma unroll
        for (int e = 0; e < NEXP; e++) { p[e] = expf(acc[e] - mx); s += p[e]; }
        float inv = 1.f / s;
#pragma unroll
        for (int e = 0; e < NEXP; e++) p[e] *= inv;

        int i0 = 0;
#pragma unroll
        for (int e = 1; e < NEXP; e++) if (p[e] > p[i0]) i0 = e;
        int i1 = (i0 == 0) ? 1 : 0;
#pragma unroll
        for (int e = 0; e < NEXP; e++) if (e != i0 && p[e] > p[i1]) i1 = e;

        g_tok_idx[2*t+0] = i0; g_tok_idx[2*t+1] = i1;
        g_tok_w[2*t+0] = p[i0]; g_tok_w[2*t+1] = p[i1];
        atomicAdd(&g_count[i0], 1);
        atomicAdd(&g_count[i1], 1);
#pragma unroll
        for (int e = 0; e < NEXP; e++) logits_out[(size_t)t * NEXP + e] = acc[e];
    }
}

// ---------------- kernel: deterministic compaction (+slot map) ----------------
__global__ void compact_kernel() {
    int e = blockIdx.x;
    int tid = threadIdx.x;
    int lane = tid & 31;
    int w = tid >> 5;

    __shared__ int warp_sum[8];
    __shared__ int base_s;

    if (tid == 0) {
        int off = 0;
        for (int i = 0; i < e; i++) off += g_count[i];
        g_offset[e] = off;
        base_s = off;
    }
    __syncthreads();

    for (int t0 = 0; t0 < NTOK; t0 += 256) {
        int t = t0 + tid;
        int i0 = g_tok_idx[2*t];
        int i1 = g_tok_idx[2*t+1];
        bool f0 = (i0 == e);
        bool f  = f0 || (i1 == e);
        unsigned m = __ballot_sync(0xffffffffu, f);
        int pos = __popc(m & ((1u << lane) - 1u));
        if (lane == 31) warp_sum[w] = __popc(m);
        __syncthreads();
        int wbase = 0;
        for (int i = 0; i < w; i++) wbase += warp_sum[i];
        if (f) {
            int p = base_s + wbase + pos;
            g_list_token[p] = t;
            g_tok_slot[2*t + (f0 ? 0 : 1)] = p;
        }
        __syncthreads();
        if (tid == 0) {
            int tot = 0;
            for (int i = 0; i < 8; i++) tot += warp_sum[i];
            base_s += tot;
        }
        __syncthreads();
    }
}

// ---------------- fp16 GEMM: block 128x256, BK=32, cp.async 4-stage ----------------
// A smem: [128 m][32 k] fp16, 64B/row, 16B-chunk swizzle kc ^= (m>>1)&3
// B smem: [32 k][256 n] fp16, 512B/row, 16B-chunk swizzle nc ^= k&7
// 8 warps (2M x 4N), warp tile 64x64, mma m16n8k16 via ldmatrix(+trans)
#define BM 128
#define BN 256
#define BK 32
#define NSTG 4
#define ABYT 8192
#define BBYT 16384
#define STGB (ABYT + BBYT)            // 24576
#define GSMEM (NSTG * STGB)           // 98304

template<int KTOT, int BSTR, bool G1>
__global__ __launch_bounds__(256, 1)
void moe_gemm(const __half* __restrict__ A0, const __half* __restrict__ Wh) {
    extern __shared__ __align__(128) uint8_t smem[];
    __shared__ int toks[BM];

    const int e   = blockIdx.z;
    const int cnt = g_count[e];
    const int m0  = blockIdx.x * BM;
    if (m0 >= cnt) return;
    const int off = g_offset[e];
    const int n0  = blockIdx.y * BN;
    const __half* We = Wh + (size_t)e * KTOT * BSTR;

    const int tid = threadIdx.x;
    if (G1) {
        if (tid < BM) toks[tid] = g_list_token[off + min(m0 + tid, cnt - 1)];
        __syncthreads();
    }

    const uint32_t sb = smem_u32(smem);

    // ---- loader precompute ----
    const __half* aptr[2];
    uint32_t dstA[2];
#pragma unroll
    for (int i = 0; i < 2; i++) {
        int c = tid + i * 256;
        int m = c >> 2, kc = c & 3;
        if (G1) aptr[i] = A0 + (size_t)toks[m] * KTOT + kc * 8;
        else    aptr[i] = A0 + (size_t)(off + min(m0 + m, cnt - 1)) * KTOT + kc * 8;
        dstA[i] = sb + m * 64 + ((kc ^ ((m >> 1) & 3)) << 4);
    }
    const __half* bptr[4];
    uint32_t dstB[4];
#pragma unroll
    for (int i = 0; i < 4; i++) {
        int c = tid + i * 256;
        int k = c >> 5, nc = c & 31;
        bptr[i] = We + (size_t)k * BSTR + n0 + nc * 8;
        dstB[i] = sb + ABYT + k * 512 + ((nc ^ (k & 7)) << 4);
    }

#define ISSUE(KT0, BB) do {                                                     \
    const uint32_t _o = (uint32_t)(BB) * STGB;                                  \
    _Pragma("unroll")                                                           \
    for (int i = 0; i < 2; i++) CP16(dstA[i] + _o, aptr[i] + (size_t)(KT0) * BK);\
    _Pragma("unroll")                                                           \
    for (int i = 0; i < 4; i++)                                                 \
        CP16(dstB[i] + _o, bptr[i] + (size_t)(KT0) * BK * BSTR);                \
    CP_COMMIT();                                                                \
} while (0)

    // ---- mma fragment addresses ----
    const int lane = tid & 31;
    const int wid  = tid >> 5;
    const int wm   = (wid & 1) * 64;
    const int wn   = (wid >> 1) * 64;
    const int gid  = lane >> 2;
    const int t4   = lane & 3;

    const int ar16 = lane & 15;
    const int rswL = (ar16 >> 1) & 3;
    const int k2b  = lane >> 4;
    uint32_t addrA[4][2];
#pragma unroll
    for (int mt = 0; mt < 4; mt++)
#pragma unroll
        for (int h = 0; h < 2; h++)
            addrA[mt][h] = sb + (wm + mt * 16 + ar16) * 64
                         + (((h * 2 + k2b) ^ rswL) << 4);
    const int kb   = lane & 15;
    const int nadd = (lane >> 4) * 8;
    uint32_t addrB[4][2];
#pragma unroll
    for (int np = 0; np < 4; np++)
#pragma unroll
        for (int h = 0; h < 2; h++) {
            int nc = (wn + np * 16 + nadd) >> 3;
            addrB[np][h] = sb + ABYT + (h * 16 + kb) * 512 + ((nc ^ (kb & 7)) << 4);
        }

    float c[4][8][4];
#pragma unroll
    for (int mt = 0; mt < 4; mt++)
#pragma unroll
        for (int nt = 0; nt < 8; nt++)
#pragma unroll
            for (int i = 0; i < 4; i++) c[mt][nt][i] = 0.f;

    // ---- prologue ----
    ISSUE(0, 0); ISSUE(1, 1); ISSUE(2, 2);

    const int KT = KTOT / BK;
    for (int kt = 0; kt < KT; kt++) {
        const int rem = KT - 1 - kt;
        if (rem >= 2)      CP_WAIT(2);
        else if (rem == 1) CP_WAIT(1);
        else               CP_WAIT(0);
        __syncthreads();
        if (kt + 3 < KT) ISSUE(kt + 3, (kt + 3) & 3);

        const uint32_t bo = (uint32_t)(kt & 3) * STGB;
#pragma unroll
        for (int h = 0; h < 2; h++) {
            uint32_t a[4][4], b[8][2];
#pragma unroll
            for (int mt = 0; mt < 4; mt++) LDSM_X4(a[mt], addrA[mt][h] + bo);
#pragma unroll
            for (int np = 0; np < 4; np++)
                LDSM_X4T(b[2*np][0], b[2*np][1], b[2*np+1][0], b[2*np+1][1],
                         addrB[np][h] + bo);
#pragma unroll
            for (int mt = 0; mt < 4; mt++)
#pragma unroll
                for (int nt = 0; nt < 8; nt++)
                    MMA_F16(c[mt][nt], a[mt], b[nt]);
        }
    }
#undef ISSUE

    // ---- epilogue ----
#pragma unroll
    for (int mt = 0; mt < 4; mt++)
#pragma unroll
        for (int nt = 0; nt < 8; nt++) {
            int col = n0 + wn + nt * 8 + t4 * 2;
#pragma unroll
            for (int hh = 0; hh < 2; hh++) {
                int row = wm + mt * 16 + gid + hh * 8;
                int gr  = m0 + row;
                if (gr < cnt) {
                    float v0 = c[mt][nt][hh * 2 + 0];
                    float v1 = c[mt][nt][hh * 2 + 1];
                    if (G1) {
                        __half2 hv = __floats2half2_rn(gelu_f(v0), gelu_f(v1));
                        *reinterpret_cast<__half2*>(
                            &g_hmid[(size_t)(off + gr) * DFF + col]) = hv;
                    } else {
                        float2 fv; fv.x = v0; fv.y = v1;
                        *reinterpret_cast<float2*>(
                            &g_ysl[(size_t)(off + gr) * HID + col]) = fv;
                    }
                }
            }
        }
}

// ---------------- kernel: combine ----------------
__global__ void combine_kernel(float* __restrict__ out) {
    int t  = blockIdx.x;
    int s0 = g_tok_slot[2 * t], s1 = g_tok_slot[2 * t + 1];
    float w0 = g_tok_w[2 * t],  w1 = g_tok_w[2 * t + 1];
    const float4* ya = reinterpret_cast<const float4*>(g_ysl + (size_t)s0 * HID);
    const float4* yb = reinterpret_cast<const float4*>(g_ysl + (size_t)s1 * HID);
    float4* o = reinterpret_cast<float4*>(out + (size_t)t * HID);
    for (int i = threadIdx.x; i < HID / 4; i += blockDim.x) {
        float4 a = ya[i], b = yb[i], r;
        r.x = w0 * a.x + w1 * b.x; r.y = w0 * a.y + w1 * b.y;
        r.z = w0 * a.z + w1 * b.z; r.w = w0 * a.w + w1 * b.w;
        o[i] = r;
    }
}

// ---------------- launch ----------------
extern "C" void kernel_launch(void* const* d_in, const int* in_sizes, int n_in,
                              void* d_out, int out_size) {
    const float* x  = (const float*)d_in[0];   // [B,S,H]
    const float* wg = (const float*)d_in[1];   // [H,E]
    const float* w1 = (const float*)d_in[2];   // [E,H,DFF]
    const float* w2 = (const float*)d_in[3];   // [E,DFF,H]
    float* out    = (float*)d_out;                    // [T,H]
    float* logits = out + (size_t)NTOK * HID;         // [T,E]

    // device addresses of __device__ scratch (host-side symbol names are NOT
    // device pointers — R8 bug was passing g_hmid directly)
    __half *xh, *w1h, *w2h, *hmid;
    cudaGetSymbolAddress((void**)&xh,   g_xh);
    cudaGetSymbolAddress((void**)&w1h,  g_w1h);
    cudaGetSymbolAddress((void**)&w2h,  g_w2h);
    cudaGetSymbolAddress((void**)&hmid, g_hmid);

    cudaFuncSetAttribute(moe_gemm<HID, DFF, true>,
                         cudaFuncAttributeMaxDynamicSharedMemorySize, GSMEM);
    cudaFuncSetAttribute(moe_gemm<DFF, HID, false>,
                         cudaFuncAttributeMaxDynamicSharedMemorySize, GSMEM);

    zcount_kernel<<<1, 32>>>();
    router_kernel<<<NTOK / 8, 256>>>(x, wg, logits);
    compact_kernel<<<NEXP, 256>>>();
    cvt_fp16_kernel<<<4096, 256>>>(x,  xh,  (size_t)NTOK * HID / 8);
    cvt_fp16_kernel<<<8192, 256>>>(w1, w1h, (size_t)NEXP * HID * DFF / 8);
    cvt_fp16_kernel<<<8192, 256>>>(w2, w2h, (size_t)NEXP * DFF * HID / 8);
    moe_gemm<HID, DFF, true>
        <<<dim3(SLOTS / BM, DFF / BN, NEXP), 256, GSMEM>>>(xh, w1h);
    moe_gemm<DFF, HID, false>
        <<<dim3(SLOTS / BM, HID / BN, NEXP), 256, GSMEM>>>(hmid, w2h);
    combine_kernel<<<NTOK, 256>>>(out);
}